// round 15
// baseline (speedup 1.0000x reference)
#include <cuda_runtime.h>
#include <cuda_bf16.h>
#include <math.h>

#define NN 50000
#define NE 800000
#define C  128

// ---------------- device scratch ----------------
static __device__ float g_P1[(size_t)NN * C];    // nf @ W1a
static __device__ float g_P2[(size_t)NN * C];    // nf @ W1b
static __device__ float g_t1[(size_t)NN * C];    // node hidden
static __device__ float g_hneigh[(size_t)NN * C];
static __device__ float g_xsum[NN * 3];
static __device__ float g_deg[NN];
static __device__ float g_red[16];

// silu via MUFU.TANH: sigma(x)=0.5*tanh(x/2)+0.5 -> silu=fma(h,tanh(h),h)
__device__ __forceinline__ float silu_f(float v) {
    float h = 0.5f * v, th;
    asm("tanh.approx.f32 %0, %1;" : "=f"(th) : "f"(h));
    return fmaf(h, th, h);
}
__device__ __forceinline__ float tf32f(float x) {
    unsigned u;
    asm("cvt.rna.tf32.f32 %0, %1;" : "=r"(u) : "f"(x));
    return __uint_as_float(u);
}
__device__ __forceinline__ unsigned fu(float x) { return __float_as_uint(x); }

__device__ __forceinline__ void mma8(float* d, const unsigned* a, unsigned b0, unsigned b1) {
    asm volatile(
        "mma.sync.aligned.m16n8k8.row.col.f32.tf32.tf32.f32 "
        "{%0,%1,%2,%3}, {%4,%5,%6,%7}, {%8,%9}, {%0,%1,%2,%3};"
        : "+f"(d[0]), "+f"(d[1]), "+f"(d[2]), "+f"(d[3])
        : "r"(a[0]), "r"(a[1]), "r"(a[2]), "r"(a[3]), "r"(b0), "r"(b1));
}

// =============== paired-k W layout ===============
// sWp[(kc*128 + c)*8 + 2*(k&3) + ((k>>2)&1)] holds W[k][c], kc = k>>3.
// B-fragment (k=t, k=t+4) for col c is one aligned float2.

// Warp-tile GEMM: A row-major in smem (optional tf32 cvt), B paired.
// Warp computes MI*16 rows x NI*8 cols; rows start at row0, cols at wc*NI*8.
template<int SA, bool CVTA, int NI, int MI>
__device__ __forceinline__ void gemm_rApB(const float* __restrict__ sA,
                                          const float* __restrict__ sWp,
                                          int kchunks, float (&acc)[MI][NI][4],
                                          int row0, int wc, int lane) {
    const int g = lane >> 2, t = lane & 3;
    const float* ar = sA + (row0 + g) * SA + t;
    const float* bb = sWp + (wc * (NI * 8) + g) * 8 + 2 * t;
#pragma unroll 4
    for (int kc = 0; kc < kchunks; ++kc) {
        const float* ap = ar + kc * 8;
        unsigned A[MI][4];
#pragma unroll
        for (int mi = 0; mi < MI; ++mi) {
            const float* am = ap + mi * 16 * SA;
            float a0 = am[0], a1 = am[8 * SA], a2 = am[4], a3 = am[8 * SA + 4];
            if (CVTA) { a0 = tf32f(a0); a1 = tf32f(a1); a2 = tf32f(a2); a3 = tf32f(a3); }
            A[mi][0] = fu(a0); A[mi][1] = fu(a1); A[mi][2] = fu(a2); A[mi][3] = fu(a3);
        }
        const float* bp = bb + kc * 1024;
#pragma unroll
        for (int ni = 0; ni < NI; ++ni) {
            float2 b = *(const float2*)(bp + ni * 64);
#pragma unroll
            for (int mi = 0; mi < MI; ++mi)
                mma8(acc[mi][ni], A[mi], fu(b.x), fu(b.y));
        }
    }
}

// load W[16384] (row-major [128][128]) into paired layout with tf32 rounding
__device__ __forceinline__ void load_paired(float* sWp, const float* W, int tid, int nthr) {
    for (int i = tid; i < 16384; i += nthr) {
        int k = i >> 7, c = i & 127;
        int pos = ((k >> 3) * 128 + c) * 8 + 2 * (k & 3) + ((k >> 2) & 1);
        sWp[pos] = tf32f(W[i]);
    }
}

// ---------------- k_npre: zero accumulators, then P1/P2 ----------------
__global__ void __launch_bounds__(512, 1)
k_npre(const float* __restrict__ nf, const float* __restrict__ W1) {
    extern __shared__ float sm[];
    float* sWa = sm;                       // 16384 (paired)
    float* sWb = sWa + 16384;              // 16384 (paired)
    float* sA  = sWb + 16384;              // 128*132 = 16896

    const int tid = threadIdx.x, lane = tid & 31, wid = tid >> 5;
    const int wr = wid & 3, wc = wid >> 2;
    const int g = lane >> 2, t = lane & 3;

    {
        const long NC = (long)NN * C, N3 = NN * 3;
        const long TOT = NC + N3 + NN + 16;
        long stride = (long)gridDim.x * blockDim.x;
        for (long i = (long)blockIdx.x * blockDim.x + tid; i < TOT; i += stride) {
            if (i < NC) g_hneigh[i] = 0.f;
            else if (i < NC + N3) g_xsum[i - NC] = 0.f;
            else if (i < NC + N3 + NN) g_deg[i - NC - N3] = 0.f;
            else g_red[i - NC - N3 - NN] = 0.f;
        }
    }

    load_paired(sWa, W1, tid, 512);
    load_paired(sWb, W1 + 16384, tid, 512);
    __syncthreads();

    const int ntiles = (NN + 127) / 128;
    for (int tile = blockIdx.x; tile < ntiles; tile += gridDim.x) {
        const int bn = tile * 128;
        for (int i = tid; i < 4096; i += 512) {
            int row = i >> 5, c4 = (i & 31) * 4;
            int n = bn + row;
            float4 v = make_float4(0.f, 0.f, 0.f, 0.f);
            if (n < NN) v = *(const float4*)&nf[(size_t)n * 128 + c4];
            float* p = &sA[row * 132 + c4];
            p[0] = tf32f(v.x); p[1] = tf32f(v.y); p[2] = tf32f(v.z); p[3] = tf32f(v.w);
        }
        __syncthreads();

        float acc[2][4][4];
#pragma unroll
        for (int mi = 0; mi < 2; ++mi)
#pragma unroll
            for (int ni = 0; ni < 4; ++ni)
#pragma unroll
                for (int q = 0; q < 4; ++q) acc[mi][ni][q] = 0.f;
        gemm_rApB<132, false, 4, 2>(sA, sWa, 16, acc, wr * 32, wc, lane);
#pragma unroll
        for (int mi = 0; mi < 2; ++mi) {
            int r = bn + wr * 32 + mi * 16 + g;
#pragma unroll
            for (int ni = 0; ni < 4; ++ni) {
                int c = wc * 32 + ni * 8 + 2 * t;
                if (r < NN)
                    *(float2*)&g_P1[(size_t)r * 128 + c] = make_float2(acc[mi][ni][0], acc[mi][ni][1]);
                if (r + 8 < NN)
                    *(float2*)&g_P1[(size_t)(r + 8) * 128 + c] = make_float2(acc[mi][ni][2], acc[mi][ni][3]);
            }
        }
#pragma unroll
        for (int mi = 0; mi < 2; ++mi)
#pragma unroll
            for (int ni = 0; ni < 4; ++ni)
#pragma unroll
                for (int q = 0; q < 4; ++q) acc[mi][ni][q] = 0.f;
        gemm_rApB<132, false, 4, 2>(sA, sWb, 16, acc, wr * 32, wc, lane);
#pragma unroll
        for (int mi = 0; mi < 2; ++mi) {
            int r = bn + wr * 32 + mi * 16 + g;
#pragma unroll
            for (int ni = 0; ni < 4; ++ni) {
                int c = wc * 32 + ni * 8 + 2 * t;
                if (r < NN)
                    *(float2*)&g_P2[(size_t)r * 128 + c] = make_float2(acc[mi][ni][0], acc[mi][ni][1]);
                if (r + 8 < NN)
                    *(float2*)&g_P2[(size_t)(r + 8) * 128 + c] = make_float2(acc[mi][ni][2], acc[mi][ni][3]);
            }
        }
        __syncthreads();
    }
}

// ---------------- k_edge: 2 groups x 8 warps, double-buffered 2-barrier pipeline ----------------
// Group grp processes 32-edge chunks. sA holds h1, sB holds h2 (separate buffers).
// Steady state: GEMM1[A] -> h2->B -> BAR_A -> GEMM2[B] + gather(n+1)->A
//               -> scatter(B) -> dot -> BAR_B -> coord scatter.
__global__ void __launch_bounds__(512, 1)
k_edge(const float* __restrict__ coord,
       const int* __restrict__ src, const int* __restrict__ dst,
       const float* __restrict__ W1, const float* __restrict__ b1,
       const float* __restrict__ W2, const float* __restrict__ b2,
       const float* __restrict__ W5, const float* __restrict__ b5,
       const float* __restrict__ W6) {
    extern __shared__ float sm[];
    float* sW2p = sm;                      // 16384 (paired)
    float* sW5p = sW2p + 16384;            // 16384 (paired)
    float* sBuf = sW5p + 16384;            // 2 groups * (4224 + 4224) = 16896
    float* sWr  = sBuf + 16896;            // 128
    float* sB1  = sWr + 128;               // 128
    float* sCWA = sB1 + 128;               // 2 groups * 32 = 64

    const int tid = threadIdx.x, lane = tid & 31, wid = tid >> 5;
    const int grp = wid >> 3;              // group 0..1 (8 warps each)
    const int w8 = wid & 7;                // warp in group
    const int wrow = w8 >> 2;              // 0..1 (16-row half)
    const int wcol = w8 & 3;               // 0..3 (32-col block)
    const int g = lane >> 2, t = lane & 3;
    const int gt = (w8 << 5) | lane;       // group-thread 0..255

    float* sA  = sBuf + grp * 8448;        // h1: 32*132
    float* sB  = sA + 4224;                // h2: 32*132
    float* sCW = sCWA + grp * 32;

    load_paired(sW2p, W2, tid, 512);
    load_paired(sW5p, W5, tid, 512);
    if (tid < 128) { sWr[tid] = W1[256 * 128 + tid]; sB1[tid] = b1[tid]; }
    if (tid < 64) sCWA[tid] = 0.f;
    __syncthreads();

    float b2lo[4], b2hi[4], b5lo[4], b5hi[4], w6lo[4], w6hi[4];
    {
        int cb = wcol * 32 + 2 * t;
#pragma unroll
        for (int ni = 0; ni < 4; ++ni) {
            b2lo[ni] = __ldg(&b2[cb + ni * 8]); b2hi[ni] = __ldg(&b2[cb + ni * 8 + 1]);
            b5lo[ni] = __ldg(&b5[cb + ni * 8]); b5hi[ni] = __ldg(&b5[cb + ni * 8 + 1]);
            w6lo[ni] = __ldg(&W6[cb + ni * 8]); w6hi[ni] = __ldg(&W6[cb + ni * 8 + 1]);
        }
    }

    const int c4 = (gt & 31) * 4;          // thread's column set
    const int r0 = gt >> 5;                // row phase 0..7 (rows r0+8k)
    const float4 w4 = *(const float4*)&sWr[c4];
    const float4 bv = *(const float4*)&sB1[c4];

    const int nchunks = NE / 32;           // 25000
    const int gstride = gridDim.x * 2;

#define EBAR() asm volatile("bar.sync %0, 256;" :: "r"(grp + 1) : "memory")

    // prologue: metadata + gather for first chunk
    int chunk = blockIdx.x * 2 + grp;
    int se, de; float dxr, dyr, dzr, rr;
    {
        int e = chunk * 32 + lane;
        se = __ldg(&src[e]); de = __ldg(&dst[e]);
        dxr = coord[se * 3 + 0] - coord[de * 3 + 0];
        dyr = coord[se * 3 + 1] - coord[de * 3 + 1];
        dzr = coord[se * 3 + 2] - coord[de * 3 + 2];
        rr = dxr * dxr + dyr * dyr + dzr * dzr;
#pragma unroll
        for (int hk = 0; hk < 2; ++hk) {
            float4 p1v[2], p2v[2]; float rv[2];
#pragma unroll
            for (int k = 0; k < 2; ++k) {
                int row = r0 + 8 * (hk * 2 + k);
                int s = __shfl_sync(0xffffffffu, se, row);
                int d = __shfl_sync(0xffffffffu, de, row);
                rv[k] = __shfl_sync(0xffffffffu, rr, row);
                p1v[k] = *(const float4*)&g_P1[(size_t)s * 128 + c4];
                p2v[k] = *(const float4*)&g_P2[(size_t)d * 128 + c4];
            }
#pragma unroll
            for (int k = 0; k < 2; ++k) {
                int row = r0 + 8 * (hk * 2 + k);
                float4 o;
                o.x = tf32f(silu_f(p1v[k].x + p2v[k].x + rv[k] * w4.x + bv.x));
                o.y = tf32f(silu_f(p1v[k].y + p2v[k].y + rv[k] * w4.y + bv.y));
                o.z = tf32f(silu_f(p1v[k].z + p2v[k].z + rv[k] * w4.z + bv.z));
                o.w = tf32f(silu_f(p1v[k].w + p2v[k].w + rv[k] * w4.w + bv.w));
                *(float4*)&sA[row * 132 + c4] = o;
            }
        }
    }
    EBAR();                                // first h1 ready

    for (; chunk < nchunks; ) {
        const int nchunk = chunk + gstride;

        // GEMM1: h2pre = h1 @ W2 + b2 (warp: 16 rows x 32 cols)
        float acc[1][4][4];
#pragma unroll
        for (int ni = 0; ni < 4; ++ni) {
            acc[0][ni][0] = b2lo[ni]; acc[0][ni][1] = b2hi[ni];
            acc[0][ni][2] = b2lo[ni]; acc[0][ni][3] = b2hi[ni];
        }
        gemm_rApB<132, false, 4, 1>(sA, sW2p, 16, acc, wrow * 16, wcol, lane);

        // write h2 = silu(acc) into sB (rows wrow*16+g, +8)
#pragma unroll
        for (int ni = 0; ni < 4; ++ni) {
            int c = wcol * 32 + ni * 8 + 2 * t;
            int r = wrow * 16 + g;
            *(float2*)&sB[r * 132 + c] =
                make_float2(silu_f(acc[0][ni][0]), silu_f(acc[0][ni][1]));
            *(float2*)&sB[(r + 8) * 132 + c] =
                make_float2(silu_f(acc[0][ni][2]), silu_f(acc[0][ni][3]));
        }

        // prefetch next chunk's metadata
        int se2 = 0, de2 = 0; float dxr2 = 0.f, dyr2 = 0.f, dzr2 = 0.f, rr2 = 0.f;
        if (nchunk < nchunks) {
            int e2 = nchunk * 32 + lane;
            se2 = __ldg(&src[e2]); de2 = __ldg(&dst[e2]);
            dxr2 = coord[se2 * 3 + 0] - coord[de2 * 3 + 0];
            dyr2 = coord[se2 * 3 + 1] - coord[de2 * 3 + 1];
            dzr2 = coord[se2 * 3 + 2] - coord[de2 * 3 + 2];
            rr2 = dxr2 * dxr2 + dyr2 * dyr2 + dzr2 * dzr2;
        }
        EBAR();                            // BAR_A: h2 done; A reads done

        // GEMM2: h3pre = h2 @ W5 + b5 (cvt A)
        float acc2[1][4][4];
#pragma unroll
        for (int ni = 0; ni < 4; ++ni) {
            acc2[0][ni][0] = b5lo[ni]; acc2[0][ni][1] = b5hi[ni];
            acc2[0][ni][2] = b5lo[ni]; acc2[0][ni][3] = b5hi[ni];
        }
        gemm_rApB<132, true, 4, 1>(sB, sW5p, 16, acc2, wrow * 16, wcol, lane);

        // gather next chunk's h1 into sA (overlaps GEMM2's latency)
        if (nchunk < nchunks) {
#pragma unroll
            for (int hk = 0; hk < 2; ++hk) {
                float4 p1v[2], p2v[2]; float rv[2];
#pragma unroll
                for (int k = 0; k < 2; ++k) {
                    int row = r0 + 8 * (hk * 2 + k);
                    int s = __shfl_sync(0xffffffffu, se2, row);
                    int d = __shfl_sync(0xffffffffu, de2, row);
                    rv[k] = __shfl_sync(0xffffffffu, rr2, row);
                    p1v[k] = *(const float4*)&g_P1[(size_t)s * 128 + c4];
                    p2v[k] = *(const float4*)&g_P2[(size_t)d * 128 + c4];
                }
#pragma unroll
                for (int k = 0; k < 2; ++k) {
                    int row = r0 + 8 * (hk * 2 + k);
                    float4 o;
                    o.x = tf32f(silu_f(p1v[k].x + p2v[k].x + rv[k] * w4.x + bv.x));
                    o.y = tf32f(silu_f(p1v[k].y + p2v[k].y + rv[k] * w4.y + bv.y));
                    o.z = tf32f(silu_f(p1v[k].z + p2v[k].z + rv[k] * w4.z + bv.z));
                    o.w = tf32f(silu_f(p1v[k].w + p2v[k].w + rv[k] * w4.w + bv.w));
                    *(float4*)&sA[row * 132 + c4] = o;
                }
            }
        }

        // scatter h2 -> g_hneigh (reads sB; current chunk's dst)
#pragma unroll
        for (int k = 0; k < 4; ++k) {
            int row = r0 + 8 * k;
            int d = __shfl_sync(0xffffffffu, de, row);
            const float4 v = *(const float4*)&sB[row * 132 + c4];
            float* p = &g_hneigh[(size_t)d * 128 + c4];
            asm volatile("red.global.add.v4.f32 [%0], {%1,%2,%3,%4};"
                         :: "l"(p), "f"(v.x), "f"(v.y), "f"(v.z), "f"(v.w) : "memory");
        }

        // dot: cw[row] = sum_c silu(h3pre)*W6[c]
        {
            float pr0 = 0.f, pr1 = 0.f;
#pragma unroll
            for (int ni = 0; ni < 4; ++ni) {
                pr0 += silu_f(acc2[0][ni][0]) * w6lo[ni] + silu_f(acc2[0][ni][1]) * w6hi[ni];
                pr1 += silu_f(acc2[0][ni][2]) * w6lo[ni] + silu_f(acc2[0][ni][3]) * w6hi[ni];
            }
            pr0 += __shfl_xor_sync(0xffffffffu, pr0, 1);
            pr0 += __shfl_xor_sync(0xffffffffu, pr0, 2);
            pr1 += __shfl_xor_sync(0xffffffffu, pr1, 1);
            pr1 += __shfl_xor_sync(0xffffffffu, pr1, 2);
            if (t == 0) {
                int r = wrow * 16 + g;
                atomicAdd(&sCW[r], pr0);
                atomicAdd(&sCW[r + 8], pr1);
            }
        }
        EBAR();                            // BAR_B: sCW done; gather done; sB reads done

        // coord scatter + degree (warp 0 of group; current chunk metadata)
        if (w8 == 0) {
            float cw = sCW[lane];
            sCW[lane] = 0.f;
            atomicAdd(&g_deg[de], 1.0f);
            float inv = 1.0f / (sqrtf(rr + 1e-6f) + 1e-6f);
            float cws = cw * inv;
            atomicAdd(&g_xsum[de * 3 + 0], cws * dxr);
            atomicAdd(&g_xsum[de * 3 + 1], cws * dyr);
            atomicAdd(&g_xsum[de * 3 + 2], cws * dzr);
        }
        // rotate metadata
        se = se2; de = de2; dxr = dxr2; dyr = dyr2; dzr = dzr2; rr = rr2;
        chunk = nchunk;
        // sCW re-zeroed above is ordered before next dot via BAR_A of next iter.
    }
#undef EBAR
}

// ---------------- k_node1: k_x prologue + t1 = silu([nf|h_neigh]@W3+b3) ----------------
__global__ void __launch_bounds__(512, 1)
k_node1(const float* __restrict__ nf, const float* __restrict__ W3,
        const float* __restrict__ b3, const float* __restrict__ coord,
        float* __restrict__ outx) {
    extern __shared__ float sm[];
    float* sWa = sm;                       // 16384 (paired)
    float* sWb = sWa + 16384;              // 16384 (paired)
    float* sA  = sWb + 16384;              // 128*132

    const int tid = threadIdx.x, lane = tid & 31, wid = tid >> 5;
    const int wr = wid & 3, wc = wid >> 2;
    const int g = lane >> 2, t = lane & 3;

    // --- fused k_x: x = coord + xsum/deg; accumulate mean/var sums ---
    {
        __shared__ float sred[6];
        if (tid < 6) sred[tid] = 0.f;
        __syncthreads();
        float ls[6] = {0.f, 0.f, 0.f, 0.f, 0.f, 0.f};
        int stride = gridDim.x * blockDim.x;
        for (int n = blockIdx.x * blockDim.x + tid; n < NN; n += stride) {
            float deg = fmaxf(g_deg[n], 1.0f);
            float invd = 1.0f / deg;
#pragma unroll
            for (int d = 0; d < 3; ++d) {
                float x = coord[n * 3 + d] + g_xsum[n * 3 + d] * invd;
                outx[n * 3 + d] = x;
                ls[d] += x;
                ls[3 + d] += x * x;
            }
        }
#pragma unroll
        for (int k = 0; k < 6; ++k) atomicAdd(&sred[k], ls[k]);
        __syncthreads();
        if (tid < 6) atomicAdd(&g_red[tid], sred[tid]);
    }

    load_paired(sWa, W3, tid, 512);
    load_paired(sWb, W3 + 16384, tid, 512);
    __syncthreads();

    float blo[4], bhi[4];
    {
        int cb = wc * 32 + 2 * t;
#pragma unroll
        for (int ni = 0; ni < 4; ++ni) {
            blo[ni] = __ldg(&b3[cb + ni * 8]);
            bhi[ni] = __ldg(&b3[cb + ni * 8 + 1]);
        }
    }

    const int ntiles = (NN + 127) / 128;
    for (int tile = blockIdx.x; tile < ntiles; tile += gridDim.x) {
        const int bn = tile * 128;
        for (int i = tid; i < 4096; i += 512) {
            int row = i >> 5, c4 = (i & 31) * 4;
            int n = bn + row;
            float4 v = make_float4(0.f, 0.f, 0.f, 0.f);
            if (n < NN) v = *(const float4*)&nf[(size_t)n * 128 + c4];
            float* p = &sA[row * 132 + c4];
            p[0] = tf32f(v.x); p[1] = tf32f(v.y); p[2] = tf32f(v.z); p[3] = tf32f(v.w);
        }
        __syncthreads();

        float acc[2][4][4];
#pragma unroll
        for (int mi = 0; mi < 2; ++mi)
#pragma unroll
            for (int ni = 0; ni < 4; ++ni) {
                acc[mi][ni][0] = blo[ni]; acc[mi][ni][1] = bhi[ni];
                acc[mi][ni][2] = blo[ni]; acc[mi][ni][3] = bhi[ni];
            }
        gemm_rApB<132, false, 4, 2>(sA, sWa, 16, acc, wr * 32, wc, lane);
        __syncthreads();
        for (int i = tid; i < 4096; i += 512) {
            int row = i >> 5, c4 = (i & 31) * 4;
            int n = bn + row;
            float4 v = make_float4(0.f, 0.f, 0.f, 0.f);
            if (n < NN) v = *(const float4*)&g_hneigh[(size_t)n * 128 + c4];
            float* p = &sA[row * 132 + c4];
            p[0] = tf32f(v.x); p[1] = tf32f(v.y); p[2] = tf32f(v.z); p[3] = tf32f(v.w);
        }
        __syncthreads();
        gemm_rApB<132, false, 4, 2>(sA, sWb, 16, acc, wr * 32, wc, lane);

#pragma unroll
        for (int mi = 0; mi < 2; ++mi) {
            int r = bn + wr * 32 + mi * 16 + g;
#pragma unroll
            for (int ni = 0; ni < 4; ++ni) {
                int c = wc * 32 + ni * 8 + 2 * t;
                if (r < NN)
                    *(float2*)&g_t1[(size_t)r * 128 + c] =
                        make_float2(tf32f(silu_f(acc[mi][ni][0])), tf32f(silu_f(acc[mi][ni][1])));
                if (r + 8 < NN)
                    *(float2*)&g_t1[(size_t)(r + 8) * 128 + c] =
                        make_float2(tf32f(silu_f(acc[mi][ni][2])), tf32f(silu_f(acc[mi][ni][3])));
            }
        }
        __syncthreads();
    }
}

// ---------------- k_node2: k_norm prologue + h = t1 @ W4 + b4 -> out ----------------
__global__ void __launch_bounds__(512, 1)
k_node2(const float* __restrict__ W4, const float* __restrict__ b4,
        float* __restrict__ outh, float* __restrict__ outx) {
    extern __shared__ float sm[];
    float* sW = sm;                        // 16384 (paired)
    float* sA = sW + 16384;                // 128*132

    const int tid = threadIdx.x, lane = tid & 31, wid = tid >> 5;
    const int wr = wid & 3, wc = wid >> 2;
    const int g = lane >> 2, t = lane & 3;

    // --- fused k_norm: normalize x (g_red complete after k_node1) ---
    {
        float mean0 = g_red[0] / (float)NN, mean1 = g_red[1] / (float)NN, mean2 = g_red[2] / (float)NN;
        float v0 = g_red[3] / (float)NN - mean0 * mean0;
        float v1 = g_red[4] / (float)NN - mean1 * mean1;
        float v2 = g_red[5] / (float)NN - mean2 * mean2;
        float is0 = 1.0f / (sqrtf(v0 + 1e-6f) + 1e-6f);
        float is1 = 1.0f / (sqrtf(v1 + 1e-6f) + 1e-6f);
        float is2 = 1.0f / (sqrtf(v2 + 1e-6f) + 1e-6f);
        int stride = gridDim.x * blockDim.x;
        for (int n = blockIdx.x * blockDim.x + tid; n < NN; n += stride) {
            outx[n * 3 + 0] = (outx[n * 3 + 0] - mean0) * is0;
            outx[n * 3 + 1] = (outx[n * 3 + 1] - mean1) * is1;
            outx[n * 3 + 2] = (outx[n * 3 + 2] - mean2) * is2;
        }
    }

    load_paired(sW, W4, tid, 512);
    __syncthreads();

    float blo[4], bhi[4];
    {
        int cb = wc * 32 + 2 * t;
#pragma unroll
        for (int ni = 0; ni < 4; ++ni) {
            blo[ni] = __ldg(&b4[cb + ni * 8]);
            bhi[ni] = __ldg(&b4[cb + ni * 8 + 1]);
        }
    }

    const int ntiles = (NN + 127) / 128;
    for (int tile = blockIdx.x; tile < ntiles; tile += gridDim.x) {
        const int bn = tile * 128;
        for (int i = tid; i < 4096; i += 512) {
            int row = i >> 5, c4 = (i & 31) * 4;
            int n = bn + row;
            float4 v = make_float4(0.f, 0.f, 0.f, 0.f);
            if (n < NN) v = *(const float4*)&g_t1[(size_t)n * 128 + c4];
            *(float4*)&sA[row * 132 + c4] = v;
        }
        __syncthreads();

        float acc[2][4][4];
#pragma unroll
        for (int mi = 0; mi < 2; ++mi)
#pragma unroll
            for (int ni = 0; ni < 4; ++ni) {
                acc[mi][ni][0] = blo[ni]; acc[mi][ni][1] = bhi[ni];
                acc[mi][ni][2] = blo[ni]; acc[mi][ni][3] = bhi[ni];
            }
        gemm_rApB<132, false, 4, 2>(sA, sW, 16, acc, wr * 32, wc, lane);

#pragma unroll
        for (int mi = 0; mi < 2; ++mi) {
            int r = bn + wr * 32 + mi * 16 + g;
#pragma unroll
            for (int ni = 0; ni < 4; ++ni) {
                int c = wc * 32 + ni * 8 + 2 * t;
                if (r < NN)
                    *(float2*)&outh[(size_t)r * 128 + c] =
                        make_float2(acc[mi][ni][0], acc[mi][ni][1]);
                if (r + 8 < NN)
                    *(float2*)&outh[(size_t)(r + 8) * 128 + c] =
                        make_float2(acc[mi][ni][2], acc[mi][ni][3]);
            }
        }
        __syncthreads();
    }
}

// ---------------- launch ----------------
extern "C" void kernel_launch(void* const* d_in, const int* in_sizes, int n_in,
                              void* d_out, int out_size) {
    const float* nf    = (const float*)d_in[0];
    const float* coord = (const float*)d_in[1];
    const int*   src   = (const int*)d_in[2];
    const int*   dst   = (const int*)d_in[3];
    const float* W1 = (const float*)d_in[4];
    const float* b1 = (const float*)d_in[5];
    const float* W2 = (const float*)d_in[6];
    const float* b2 = (const float*)d_in[7];
    const float* W3 = (const float*)d_in[8];
    const float* b3 = (const float*)d_in[9];
    const float* W4 = (const float*)d_in[10];
    const float* b4 = (const float*)d_in[11];
    const float* W5 = (const float*)d_in[12];
    const float* b5 = (const float*)d_in[13];
    const float* W6 = (const float*)d_in[14];

    float* outh = (float*)d_out;
    float* outx = outh + (size_t)NN * C;

    const int SM_NPRE = (16384 * 2 + 16896) * 4;
    const int SM_EDGE = (16384 * 2 + 16896 + 128 * 2 + 64) * 4;
    const int SM_N1   = (16384 * 2 + 16896) * 4;
    const int SM_N2   = (16384 + 16896) * 4;

    cudaFuncSetAttribute(k_npre,  cudaFuncAttributeMaxDynamicSharedMemorySize, SM_NPRE);
    cudaFuncSetAttribute(k_edge,  cudaFuncAttributeMaxDynamicSharedMemorySize, SM_EDGE);
    cudaFuncSetAttribute(k_node1, cudaFuncAttributeMaxDynamicSharedMemorySize, SM_N1);
    cudaFuncSetAttribute(k_node2, cudaFuncAttributeMaxDynamicSharedMemorySize, SM_N2);

    k_npre<<<148, 512, SM_NPRE>>>(nf, W1);
    k_edge<<<148, 512, SM_EDGE>>>(coord, src, dst, W1, b1, W2, b2, W5, b5, W6);
    k_node1<<<148, 512, SM_N1>>>(nf, W3, b3, coord, outx);
    k_node2<<<148, 512, SM_N2>>>(W4, b4, outh, outx);
}